// round 14
// baseline (speedup 1.0000x reference)
#include <cuda_runtime.h>
#include <cuda_fp8.h>
#include <cstdint>
#include <cstddef>

// Problem dims (x: [8,2048,4096] fp32, w: [4096,4096] fp32)
#define K_DIM 4096
#define N_DIM 4096
#define M_MAX 16384
#define FP8MAX 448.0f

// ---------------- device scratch (static, allocation-free) ----------------
__device__ unsigned g_amax_bits[2];                                   // [0]=x, [1]=w
__device__ __align__(128) unsigned char g_Aq[(size_t)M_MAX * K_DIM];  // xq, [M,K] K-major
__device__ __align__(128) unsigned char g_Bq[(size_t)N_DIM * K_DIM];  // wq^T, [N,K] K-major

// ---------------- PTX helpers (NON arch-conditional only) ----------------
__device__ __forceinline__ uint32_t smem_u32(const void* p) {
    uint32_t a;
    asm("{ .reg .u64 t; cvta.to.shared.u64 t, %1; cvt.u32.u64 %0, t; }" : "=r"(a) : "l"(p));
    return a;
}
#define CP16(d, s) asm volatile("cp.async.cg.shared.global [%0], [%1], 16;" :: "r"(d), "l"(s) : "memory")
#define CP_COMMIT() asm volatile("cp.async.commit_group;" ::: "memory")
#define CP_WAIT1()  asm volatile("cp.async.wait_group 1;" ::: "memory")

#define LDM_X4(r0, r1, r2, r3, a)                                              \
    asm volatile("ldmatrix.sync.aligned.m8n8.x4.shared.b16 {%0,%1,%2,%3}, [%4];" \
                 : "=r"(r0), "=r"(r1), "=r"(r2), "=r"(r3) : "r"(a))

// fp8 e4m3 MMA, m16n8k32, fp32 accumulate (plain sm_89+ PTX, legacy tensor pipe)
#define MMA_E4M3(d, a, b0, b1)                                                      \
    asm volatile("mma.sync.aligned.m16n8k32.row.col.f32.e4m3.e4m3.f32 "             \
                 "{%0,%1,%2,%3}, {%4,%5,%6,%7}, {%8,%9}, {%0,%1,%2,%3};"            \
                 : "+f"((d)[0]), "+f"((d)[1]), "+f"((d)[2]), "+f"((d)[3])           \
                 : "r"((a)[0]), "r"((a)[1]), "r"((a)[2]), "r"((a)[3]),              \
                   "r"(b0), "r"(b1))

__device__ __forceinline__ float fmax4(float4 v) {
    return fmaxf(fmaxf(fabsf(v.x), fabsf(v.y)), fmaxf(fabsf(v.z), fabsf(v.w)));
}
__device__ __forceinline__ uchar4 quant4(float4 v, float s) {
    uchar4 q;
    q.x = __nv_cvt_float_to_fp8(v.x * s, __NV_SATFINITE, __NV_E4M3);
    q.y = __nv_cvt_float_to_fp8(v.y * s, __NV_SATFINITE, __NV_E4M3);
    q.z = __nv_cvt_float_to_fp8(v.z * s, __NV_SATFINITE, __NV_E4M3);
    q.w = __nv_cvt_float_to_fp8(v.w * s, __NV_SATFINITE, __NV_E4M3);
    return q;
}

// ---------------- pre-pass kernels ----------------
// fused amax over both tensors: blocks [0, bx) -> x (streaming reads),
// blocks [bx, gridDim) -> w (DEFAULT policy reads: w stays L2-resident for
// quant_both, which re-reads it shortly after -> saves ~67MB of DRAM).
// MLP=8. R12-measured best: grid 2560, split 2048:512.
__global__ void amax2_kernel(const float4* __restrict__ x, int n4x,
                             const float4* __restrict__ w, int n4w, int bx) {
    const bool isW = (int)blockIdx.x >= bx;
    const float4* p = isW ? w : x;
    const int n4 = isW ? n4w : n4x;
    const int nb = isW ? (gridDim.x - bx) : bx;
    const int b = isW ? (blockIdx.x - bx) : blockIdx.x;

    const int stride = nb * blockDim.x;
    int i = b * blockDim.x + threadIdx.x;
    float mm[8] = {0, 0, 0, 0, 0, 0, 0, 0};
    if (isW) {
        for (; i + 7 * stride < n4; i += 8 * stride) {
            #pragma unroll
            for (int j = 0; j < 8; j++) mm[j] = fmaxf(mm[j], fmax4(p[i + j * stride]));
        }
        for (; i < n4; i += stride) mm[0] = fmaxf(mm[0], fmax4(p[i]));
    } else {
        for (; i + 7 * stride < n4; i += 8 * stride) {
            #pragma unroll
            for (int j = 0; j < 8; j++) mm[j] = fmaxf(mm[j], fmax4(__ldcs(&p[i + j * stride])));
        }
        for (; i < n4; i += stride) mm[0] = fmaxf(mm[0], fmax4(__ldcs(&p[i])));
    }
    float m = 0.0f;
    #pragma unroll
    for (int j = 0; j < 8; j++) m = fmaxf(m, mm[j]);

    #pragma unroll
    for (int o = 16; o; o >>= 1) m = fmaxf(m, __shfl_xor_sync(0xffffffffu, m, o));
    __shared__ float sm[8];
    if ((threadIdx.x & 31) == 0) sm[threadIdx.x >> 5] = m;
    __syncthreads();
    if (threadIdx.x < 8) {
        m = sm[threadIdx.x];
        #pragma unroll
        for (int o = 4; o; o >>= 1) m = fmaxf(m, __shfl_xor_sync(0xffu, m, o));
        if (threadIdx.x == 0) atomicMax(&g_amax_bits[isW ? 1 : 0], __float_as_uint(m));
    }
}

// fused quantization: blocks [0, bx) quantize x -> g_Aq (MLP=4 elementwise);
// blocks [bx, bx+4096) quantize + transpose one 64x64 tile of w -> g_Bq
// (w reads hit L2 thanks to amax's default-policy read).
__global__ void quant_both_kernel(const float4* __restrict__ x, int n4x,
                                  const float* __restrict__ w, int bx) {
    __shared__ unsigned char s[64][68];
    const int t = threadIdx.x;  // 256

    if ((int)blockIdx.x < bx) {
        const float sx = FP8MAX / fmaxf(__uint_as_float(g_amax_bits[0]), 1e-12f);
        uchar4* dst = reinterpret_cast<uchar4*>(g_Aq);
        const int stride = bx * blockDim.x;
        int i = blockIdx.x * blockDim.x + t;
        for (; i + 3 * stride < n4x; i += 4 * stride) {
            float4 v0 = __ldcs(&x[i]);
            float4 v1 = __ldcs(&x[i + stride]);
            float4 v2 = __ldcs(&x[i + 2 * stride]);
            float4 v3 = __ldcs(&x[i + 3 * stride]);
            dst[i]              = quant4(v0, sx);
            dst[i + stride]     = quant4(v1, sx);
            dst[i + 2 * stride] = quant4(v2, sx);
            dst[i + 3 * stride] = quant4(v3, sx);
        }
        for (; i < n4x; i += stride) dst[i] = quant4(__ldcs(&x[i]), sx);
        return;
    }

    const float sc = FP8MAX / fmaxf(__uint_as_float(g_amax_bits[1]), 1e-12f);
    const int bw = blockIdx.x - bx;          // 0..4095
    const int n0 = (bw & 63) * 64;
    const int k0 = (bw >> 6) * 64;
    const int kl = t >> 2, q = t & 3;
    const float4* src = reinterpret_cast<const float4*>(w + (size_t)(k0 + kl) * N_DIM + n0 + q * 16);
    #pragma unroll
    for (int j = 0; j < 4; j++) {
        float4 v = src[j];               // L2 hit expected
        int nn = q * 16 + j * 4;
        s[kl][nn + 0] = __nv_cvt_float_to_fp8(v.x * sc, __NV_SATFINITE, __NV_E4M3);
        s[kl][nn + 1] = __nv_cvt_float_to_fp8(v.y * sc, __NV_SATFINITE, __NV_E4M3);
        s[kl][nn + 2] = __nv_cvt_float_to_fp8(v.z * sc, __NV_SATFINITE, __NV_E4M3);
        s[kl][nn + 3] = __nv_cvt_float_to_fp8(v.w * sc, __NV_SATFINITE, __NV_E4M3);
    }
    __syncthreads();
    const int nl = t >> 2;  // q = t & 3
    unsigned char b[16];
    #pragma unroll
    for (int j = 0; j < 16; j++) b[j] = s[q * 16 + j][nl];
    uint4 o;
    o.x = (uint32_t)b[0]  | ((uint32_t)b[1]  << 8) | ((uint32_t)b[2]  << 16) | ((uint32_t)b[3]  << 24);
    o.y = (uint32_t)b[4]  | ((uint32_t)b[5]  << 8) | ((uint32_t)b[6]  << 16) | ((uint32_t)b[7]  << 24);
    o.z = (uint32_t)b[8]  | ((uint32_t)b[9]  << 8) | ((uint32_t)b[10] << 16) | ((uint32_t)b[11] << 24);
    o.w = (uint32_t)b[12] | ((uint32_t)b[13] << 8) | ((uint32_t)b[14] << 16) | ((uint32_t)b[15] << 24);
    *reinterpret_cast<uint4*>(g_Bq + (size_t)(n0 + nl) * K_DIM + k0 + q * 16) = o;
}

// ---------------- GEMM: fp8 mma.sync, 2-stage cp.async, 64x256x128 tile, 2 CTA/SM ----------
// (Winner config, byte-frozen: tensor pipe measured at its effective HW rate
// (~60%, invariant across 5 scheduling variants); GEMM is at roofline for
// legacy mma.sync e4m3 on this toolchain.)
static constexpr int BM = 64, BN = 256, BK = 128, STAGES = 2;
static constexpr int ROWB = 144;                       // padded row stride (bytes)
static constexpr int A_BYTES = BM * ROWB;              // 9216
static constexpr int B_BYTES = BN * ROWB;              // 36864
static constexpr int ST_BYTES = A_BYTES + B_BYTES;     // 46080
static constexpr int SMEM_DYN = STAGES * ST_BYTES;     // 92160 -> 2 CTAs/SM
static constexpr int NCHUNK = K_DIM / BK;              // 32

__global__ void __launch_bounds__(256, 2) gemm_kernel(float* __restrict__ out) {
    extern __shared__ char smem_raw[];
    const uint32_t base = smem_u32(smem_raw);
    const int tid = threadIdx.x, wid = tid >> 5, lane = tid & 31;
    const int m0 = blockIdx.x * BM, n0 = blockIdx.y * BN;  // M fastest -> B tile L2-resident

    // warp tile: wm in {0,32}, wn in {0,64,128,192}
    const int wm = (wid & 1) * 32;
    const int wn = (wid >> 1) * 64;

    // ---- loader geometry ----
    const int rowb = tid >> 3;            // 0..31
    const int col  = (tid & 7) * 16;
    const unsigned char* aP = g_Aq + (size_t)(m0 + rowb) * K_DIM + col;
    const unsigned char* bP = g_Bq + (size_t)(n0 + rowb) * K_DIM + col;
    const uint32_t dA = (uint32_t)(rowb * ROWB + col);
    const uint32_t dB = (uint32_t)(A_BYTES + rowb * ROWB + col);

    // ---- ldmatrix lane address components ----
    const int a_row = (lane & 7) + ((lane >> 3) & 1) * 8;
    const int a_kh  = (lane >> 4) * 16;
    const int b_row = (lane & 7) + (lane >> 4) * 8;
    const int b_kh  = ((lane >> 3) & 1) * 16;
    const uint32_t a_lane_off = (uint32_t)(wm + a_row) * ROWB + a_kh;
    const uint32_t b_lane_off = (uint32_t)(wn + b_row) * ROWB + b_kh + A_BYTES;

    float acc[2][8][4];
    #pragma unroll
    for (int i = 0; i < 2; i++)
        #pragma unroll
        for (int j = 0; j < 8; j++)
            #pragma unroll
            for (int r = 0; r < 4; r++) acc[i][j][r] = 0.0f;

    auto load_chunk = [&](int kc, int s) {
        const uint32_t d = base + s * ST_BYTES;
        const unsigned char* a = aP + (size_t)kc * BK;
        const unsigned char* b = bP + (size_t)kc * BK;
        CP16(d + dA, a);
        CP16(d + dA + 32 * ROWB, a + (size_t)32 * K_DIM);
        #pragma unroll
        for (int j = 0; j < 8; j++)
            CP16(d + dB + j * (32 * ROWB), b + (size_t)j * 32 * K_DIM);
    };

    load_chunk(0, 0); CP_COMMIT();
    load_chunk(1, 1); CP_COMMIT();

    uint32_t afr[2][2][4];   // [buf][mf][reg]
    uint32_t bfr[2][4][4];   // [buf][np][reg]

    for (int cc = 0; cc < NCHUNK; cc++) {
        CP_WAIT1();              // my group for chunk cc retired
        __syncthreads();         // everyone's group for chunk cc retired

        const uint32_t St = base + (cc & 1) * ST_BYTES;

        // prologue: fragments for ks=0
        #pragma unroll
        for (int mf = 0; mf < 2; mf++)
            LDM_X4(afr[0][mf][0], afr[0][mf][1], afr[0][mf][2], afr[0][mf][3],
                   St + a_lane_off + (uint32_t)mf * (16 * ROWB));
        #pragma unroll
        for (int np = 0; np < 4; np++)
            LDM_X4(bfr[0][np][0], bfr[0][np][1], bfr[0][np][2], bfr[0][np][3],
                   St + b_lane_off + (uint32_t)np * (16 * ROWB));

        #pragma unroll
        for (int ks = 0; ks < 4; ks++) {
            const int cur = ks & 1, nxt = cur ^ 1;
            if (ks < 3) {
                #pragma unroll
                for (int mf = 0; mf < 2; mf++)
                    LDM_X4(afr[nxt][mf][0], afr[nxt][mf][1], afr[nxt][mf][2], afr[nxt][mf][3],
                           St + a_lane_off + (uint32_t)mf * (16 * ROWB) + (ks + 1) * 32);
                #pragma unroll
                for (int np = 0; np < 4; np++)
                    LDM_X4(bfr[nxt][np][0], bfr[nxt][np][1], bfr[nxt][np][2], bfr[nxt][np][3],
                           St + b_lane_off + (uint32_t)np * (16 * ROWB) + (ks + 1) * 32);
            }
            #pragma unroll
            for (int mf = 0; mf < 2; mf++)
                #pragma unroll
                for (int np = 0; np < 4; np++) {
                    MMA_E4M3(acc[mf][2 * np],     afr[cur][mf], bfr[cur][np][0], bfr[cur][np][1]);
                    MMA_E4M3(acc[mf][2 * np + 1], afr[cur][mf], bfr[cur][np][2], bfr[cur][np][3]);
                }
        }

        __syncthreads();         // all warps done reading buf (cc&1) before overwrite
        if (cc + 2 < NCHUNK) load_chunk(cc + 2, cc & 1);
        CP_COMMIT();             // commit every iter keeps group FIFO aligned
    }

    // dequant factor: (1/s_x)*(1/s_w)
    const float inv = (fmaxf(__uint_as_float(g_amax_bits[0]), 1e-12f) * (1.0f / FP8MAX)) *
                      (fmaxf(__uint_as_float(g_amax_bits[1]), 1e-12f) * (1.0f / FP8MAX));

    const int g = lane >> 2, t = lane & 3;
    #pragma unroll
    for (int mf = 0; mf < 2; mf++) {
        const int r0 = m0 + wm + mf * 16 + g;
        float* row0 = out + (size_t)r0 * N_DIM + n0 + wn;
        float* row1 = row0 + (size_t)8 * N_DIM;
        #pragma unroll
        for (int nf = 0; nf < 8; nf++) {
            const int c = nf * 8 + 2 * t;
            float2 v0 = {acc[mf][nf][0] * inv, acc[mf][nf][1] * inv};
            float2 v1 = {acc[mf][nf][2] * inv, acc[mf][nf][3] * inv};
            *reinterpret_cast<float2*>(row0 + c) = v0;
            *reinterpret_cast<float2*>(row1 + c) = v1;
        }
    }
}

// ---------------- launcher ----------------
extern "C" void kernel_launch(void* const* d_in, const int* in_sizes, int n_in,
                              void* d_out, int out_size) {
    const float* x = (const float*)d_in[0];
    const float* w = (const float*)d_in[1];
    float* out = (float*)d_out;

    int M = in_sizes[0] / K_DIM;  // 16384
    int n4x = in_sizes[0] / 4;
    int n4w = in_sizes[1] / 4;

    cudaFuncSetAttribute(gemm_kernel, cudaFuncAttributeMaxDynamicSharedMemorySize, SMEM_DYN);

    void* amax_ptr = nullptr;
    cudaGetSymbolAddress(&amax_ptr, g_amax_bits);
    cudaMemsetAsync(amax_ptr, 0, 2 * sizeof(unsigned));

    // R12-measured best amax config: 2560 blocks, split 2048:512
    amax2_kernel<<<2560, 256>>>((const float4*)x, n4x, (const float4*)w, n4w, 2048);
    quant_both_kernel<<<2048 + 4096, 256>>>((const float4*)x, n4x, w, 2048);
    gemm_kernel<<<dim3(M / BM, N_DIM / BN), 256, SMEM_DYN>>>(out);
}

// round 15
// speedup vs baseline: 1.0023x; 1.0023x over previous
#include <cuda_runtime.h>
#include <cuda_fp8.h>
#include <cstdint>
#include <cstddef>

// Problem dims (x: [8,2048,4096] fp32, w: [4096,4096] fp32)
#define K_DIM 4096
#define N_DIM 4096
#define M_MAX 16384
#define FP8MAX 448.0f

// ---------------- device scratch (static, allocation-free) ----------------
__device__ unsigned g_amax_bits[2];                                   // [0]=x, [1]=w
__device__ __align__(128) unsigned char g_Aq[(size_t)M_MAX * K_DIM];  // xq, [M,K] K-major
__device__ __align__(128) unsigned char g_Bq[(size_t)N_DIM * K_DIM];  // wq^T, [N,K] K-major

// ---------------- PTX helpers (NON arch-conditional only) ----------------
__device__ __forceinline__ uint32_t smem_u32(const void* p) {
    uint32_t a;
    asm("{ .reg .u64 t; cvta.to.shared.u64 t, %1; cvt.u32.u64 %0, t; }" : "=r"(a) : "l"(p));
    return a;
}
#define CP16(d, s) asm volatile("cp.async.cg.shared.global [%0], [%1], 16;" :: "r"(d), "l"(s) : "memory")
#define CP_COMMIT() asm volatile("cp.async.commit_group;" ::: "memory")
#define CP_WAIT1()  asm volatile("cp.async.wait_group 1;" ::: "memory")

#define LDM_X4(r0, r1, r2, r3, a)                                              \
    asm volatile("ldmatrix.sync.aligned.m8n8.x4.shared.b16 {%0,%1,%2,%3}, [%4];" \
                 : "=r"(r0), "=r"(r1), "=r"(r2), "=r"(r3) : "r"(a))

// fp8 e4m3 MMA, m16n8k32, fp32 accumulate (plain sm_89+ PTX, legacy tensor pipe)
#define MMA_E4M3(d, a, b0, b1)                                                      \
    asm volatile("mma.sync.aligned.m16n8k32.row.col.f32.e4m3.e4m3.f32 "             \
                 "{%0,%1,%2,%3}, {%4,%5,%6,%7}, {%8,%9}, {%0,%1,%2,%3};"            \
                 : "+f"((d)[0]), "+f"((d)[1]), "+f"((d)[2]), "+f"((d)[3])           \
                 : "r"((a)[0]), "r"((a)[1]), "r"((a)[2]), "r"((a)[3]),              \
                   "r"(b0), "r"(b1))

__device__ __forceinline__ float fmax4(float4 v) {
    return fmaxf(fmaxf(fabsf(v.x), fabsf(v.y)), fmaxf(fabsf(v.z), fabsf(v.w)));
}
__device__ __forceinline__ uchar4 quant4(float4 v, float s) {
    uchar4 q;
    q.x = __nv_cvt_float_to_fp8(v.x * s, __NV_SATFINITE, __NV_E4M3);
    q.y = __nv_cvt_float_to_fp8(v.y * s, __NV_SATFINITE, __NV_E4M3);
    q.z = __nv_cvt_float_to_fp8(v.z * s, __NV_SATFINITE, __NV_E4M3);
    q.w = __nv_cvt_float_to_fp8(v.w * s, __NV_SATFINITE, __NV_E4M3);
    return q;
}

// ---------------- pre-pass kernels ----------------
// fused amax over both tensors: blocks [0, bx) -> x (streaming reads),
// blocks [bx, gridDim) -> w (DEFAULT policy reads: w stays L2-resident for
// quant_both, which re-reads it shortly after -> saves ~67MB of DRAM).
// MLP=8. R12-measured best: grid 2560, split 2048:512.
__global__ void amax2_kernel(const float4* __restrict__ x, int n4x,
                             const float4* __restrict__ w, int n4w, int bx) {
    const bool isW = (int)blockIdx.x >= bx;
    const float4* p = isW ? w : x;
    const int n4 = isW ? n4w : n4x;
    const int nb = isW ? (gridDim.x - bx) : bx;
    const int b = isW ? (blockIdx.x - bx) : blockIdx.x;

    const int stride = nb * blockDim.x;
    int i = b * blockDim.x + threadIdx.x;
    float mm[8] = {0, 0, 0, 0, 0, 0, 0, 0};
    if (isW) {
        for (; i + 7 * stride < n4; i += 8 * stride) {
            #pragma unroll
            for (int j = 0; j < 8; j++) mm[j] = fmaxf(mm[j], fmax4(p[i + j * stride]));
        }
        for (; i < n4; i += stride) mm[0] = fmaxf(mm[0], fmax4(p[i]));
    } else {
        for (; i + 7 * stride < n4; i += 8 * stride) {
            #pragma unroll
            for (int j = 0; j < 8; j++) mm[j] = fmaxf(mm[j], fmax4(__ldcs(&p[i + j * stride])));
        }
        for (; i < n4; i += stride) mm[0] = fmaxf(mm[0], fmax4(__ldcs(&p[i])));
    }
    float m = 0.0f;
    #pragma unroll
    for (int j = 0; j < 8; j++) m = fmaxf(m, mm[j]);

    #pragma unroll
    for (int o = 16; o; o >>= 1) m = fmaxf(m, __shfl_xor_sync(0xffffffffu, m, o));
    __shared__ float sm[8];
    if ((threadIdx.x & 31) == 0) sm[threadIdx.x >> 5] = m;
    __syncthreads();
    if (threadIdx.x < 8) {
        m = sm[threadIdx.x];
        #pragma unroll
        for (int o = 4; o; o >>= 1) m = fmaxf(m, __shfl_xor_sync(0xffu, m, o));
        if (threadIdx.x == 0) atomicMax(&g_amax_bits[isW ? 1 : 0], __float_as_uint(m));
    }
}

// fused quantization: blocks [0, bx) quantize x -> g_Aq (MLP=4 elementwise);
// blocks [bx, bx+4096) quantize + transpose one 64x64 tile of w -> g_Bq
// (w reads hit L2 thanks to amax's default-policy read).
// bx=4096 this round: finer x-block granularity interleaves the DRAM-bound
// x-stream with the L2-bound w-tiles and shrinks the drain tail.
__global__ void quant_both_kernel(const float4* __restrict__ x, int n4x,
                                  const float* __restrict__ w, int bx) {
    __shared__ unsigned char s[64][68];
    const int t = threadIdx.x;  // 256

    if ((int)blockIdx.x < bx) {
        const float sx = FP8MAX / fmaxf(__uint_as_float(g_amax_bits[0]), 1e-12f);
        uchar4* dst = reinterpret_cast<uchar4*>(g_Aq);
        const int stride = bx * blockDim.x;
        int i = blockIdx.x * blockDim.x + t;
        for (; i + 3 * stride < n4x; i += 4 * stride) {
            float4 v0 = __ldcs(&x[i]);
            float4 v1 = __ldcs(&x[i + stride]);
            float4 v2 = __ldcs(&x[i + 2 * stride]);
            float4 v3 = __ldcs(&x[i + 3 * stride]);
            dst[i]              = quant4(v0, sx);
            dst[i + stride]     = quant4(v1, sx);
            dst[i + 2 * stride] = quant4(v2, sx);
            dst[i + 3 * stride] = quant4(v3, sx);
        }
        for (; i < n4x; i += stride) dst[i] = quant4(__ldcs(&x[i]), sx);
        return;
    }

    const float sc = FP8MAX / fmaxf(__uint_as_float(g_amax_bits[1]), 1e-12f);
    const int bw = blockIdx.x - bx;          // 0..4095
    const int n0 = (bw & 63) * 64;
    const int k0 = (bw >> 6) * 64;
    const int kl = t >> 2, q = t & 3;
    const float4* src = reinterpret_cast<const float4*>(w + (size_t)(k0 + kl) * N_DIM + n0 + q * 16);
    #pragma unroll
    for (int j = 0; j < 4; j++) {
        float4 v = src[j];               // L2 hit expected
        int nn = q * 16 + j * 4;
        s[kl][nn + 0] = __nv_cvt_float_to_fp8(v.x * sc, __NV_SATFINITE, __NV_E4M3);
        s[kl][nn + 1] = __nv_cvt_float_to_fp8(v.y * sc, __NV_SATFINITE, __NV_E4M3);
        s[kl][nn + 2] = __nv_cvt_float_to_fp8(v.z * sc, __NV_SATFINITE, __NV_E4M3);
        s[kl][nn + 3] = __nv_cvt_float_to_fp8(v.w * sc, __NV_SATFINITE, __NV_E4M3);
    }
    __syncthreads();
    const int nl = t >> 2;  // q = t & 3
    unsigned char b[16];
    #pragma unroll
    for (int j = 0; j < 16; j++) b[j] = s[q * 16 + j][nl];
    uint4 o;
    o.x = (uint32_t)b[0]  | ((uint32_t)b[1]  << 8) | ((uint32_t)b[2]  << 16) | ((uint32_t)b[3]  << 24);
    o.y = (uint32_t)b[4]  | ((uint32_t)b[5]  << 8) | ((uint32_t)b[6]  << 16) | ((uint32_t)b[7]  << 24);
    o.z = (uint32_t)b[8]  | ((uint32_t)b[9]  << 8) | ((uint32_t)b[10] << 16) | ((uint32_t)b[11] << 24);
    o.w = (uint32_t)b[12] | ((uint32_t)b[13] << 8) | ((uint32_t)b[14] << 16) | ((uint32_t)b[15] << 24);
    *reinterpret_cast<uint4*>(g_Bq + (size_t)(n0 + nl) * K_DIM + k0 + q * 16) = o;
}

// ---------------- GEMM: fp8 mma.sync, 2-stage cp.async, 64x256x128 tile, 2 CTA/SM ----------
// (Winner config, byte-frozen: tensor pipe measured at its effective HW rate
// (~60%, invariant across 5 scheduling variants); GEMM is at roofline for
// legacy mma.sync e4m3 on this toolchain.)
static constexpr int BM = 64, BN = 256, BK = 128, STAGES = 2;
static constexpr int ROWB = 144;                       // padded row stride (bytes)
static constexpr int A_BYTES = BM * ROWB;              // 9216
static constexpr int B_BYTES = BN * ROWB;              // 36864
static constexpr int ST_BYTES = A_BYTES + B_BYTES;     // 46080
static constexpr int SMEM_DYN = STAGES * ST_BYTES;     // 92160 -> 2 CTAs/SM
static constexpr int NCHUNK = K_DIM / BK;              // 32

__global__ void __launch_bounds__(256, 2) gemm_kernel(float* __restrict__ out) {
    extern __shared__ char smem_raw[];
    const uint32_t base = smem_u32(smem_raw);
    const int tid = threadIdx.x, wid = tid >> 5, lane = tid & 31;
    const int m0 = blockIdx.x * BM, n0 = blockIdx.y * BN;  // M fastest -> B tile L2-resident

    // warp tile: wm in {0,32}, wn in {0,64,128,192}
    const int wm = (wid & 1) * 32;
    const int wn = (wid >> 1) * 64;

    // ---- loader geometry ----
    const int rowb = tid >> 3;            // 0..31
    const int col  = (tid & 7) * 16;
    const unsigned char* aP = g_Aq + (size_t)(m0 + rowb) * K_DIM + col;
    const unsigned char* bP = g_Bq + (size_t)(n0 + rowb) * K_DIM + col;
    const uint32_t dA = (uint32_t)(rowb * ROWB + col);
    const uint32_t dB = (uint32_t)(A_BYTES + rowb * ROWB + col);

    // ---- ldmatrix lane address components ----
    const int a_row = (lane & 7) + ((lane >> 3) & 1) * 8;
    const int a_kh  = (lane >> 4) * 16;
    const int b_row = (lane & 7) + (lane >> 4) * 8;
    const int b_kh  = ((lane >> 3) & 1) * 16;
    const uint32_t a_lane_off = (uint32_t)(wm + a_row) * ROWB + a_kh;
    const uint32_t b_lane_off = (uint32_t)(wn + b_row) * ROWB + b_kh + A_BYTES;

    float acc[2][8][4];
    #pragma unroll
    for (int i = 0; i < 2; i++)
        #pragma unroll
        for (int j = 0; j < 8; j++)
            #pragma unroll
            for (int r = 0; r < 4; r++) acc[i][j][r] = 0.0f;

    auto load_chunk = [&](int kc, int s) {
        const uint32_t d = base + s * ST_BYTES;
        const unsigned char* a = aP + (size_t)kc * BK;
        const unsigned char* b = bP + (size_t)kc * BK;
        CP16(d + dA, a);
        CP16(d + dA + 32 * ROWB, a + (size_t)32 * K_DIM);
        #pragma unroll
        for (int j = 0; j < 8; j++)
            CP16(d + dB + j * (32 * ROWB), b + (size_t)j * 32 * K_DIM);
    };

    load_chunk(0, 0); CP_COMMIT();
    load_chunk(1, 1); CP_COMMIT();

    uint32_t afr[2][2][4];   // [buf][mf][reg]
    uint32_t bfr[2][4][4];   // [buf][np][reg]

    for (int cc = 0; cc < NCHUNK; cc++) {
        CP_WAIT1();              // my group for chunk cc retired
        __syncthreads();         // everyone's group for chunk cc retired

        const uint32_t St = base + (cc & 1) * ST_BYTES;

        // prologue: fragments for ks=0
        #pragma unroll
        for (int mf = 0; mf < 2; mf++)
            LDM_X4(afr[0][mf][0], afr[0][mf][1], afr[0][mf][2], afr[0][mf][3],
                   St + a_lane_off + (uint32_t)mf * (16 * ROWB));
        #pragma unroll
        for (int np = 0; np < 4; np++)
            LDM_X4(bfr[0][np][0], bfr[0][np][1], bfr[0][np][2], bfr[0][np][3],
                   St + b_lane_off + (uint32_t)np * (16 * ROWB));

        #pragma unroll
        for (int ks = 0; ks < 4; ks++) {
            const int cur = ks & 1, nxt = cur ^ 1;
            if (ks < 3) {
                #pragma unroll
                for (int mf = 0; mf < 2; mf++)
                    LDM_X4(afr[nxt][mf][0], afr[nxt][mf][1], afr[nxt][mf][2], afr[nxt][mf][3],
                           St + a_lane_off + (uint32_t)mf * (16 * ROWB) + (ks + 1) * 32);
                #pragma unroll
                for (int np = 0; np < 4; np++)
                    LDM_X4(bfr[nxt][np][0], bfr[nxt][np][1], bfr[nxt][np][2], bfr[nxt][np][3],
                           St + b_lane_off + (uint32_t)np * (16 * ROWB) + (ks + 1) * 32);
            }
            #pragma unroll
            for (int mf = 0; mf < 2; mf++)
                #pragma unroll
                for (int np = 0; np < 4; np++) {
                    MMA_E4M3(acc[mf][2 * np],     afr[cur][mf], bfr[cur][np][0], bfr[cur][np][1]);
                    MMA_E4M3(acc[mf][2 * np + 1], afr[cur][mf], bfr[cur][np][2], bfr[cur][np][3]);
                }
        }

        __syncthreads();         // all warps done reading buf (cc&1) before overwrite
        if (cc + 2 < NCHUNK) load_chunk(cc + 2, cc & 1);
        CP_COMMIT();             // commit every iter keeps group FIFO aligned
    }

    // dequant factor: (1/s_x)*(1/s_w)
    const float inv = (fmaxf(__uint_as_float(g_amax_bits[0]), 1e-12f) * (1.0f / FP8MAX)) *
                      (fmaxf(__uint_as_float(g_amax_bits[1]), 1e-12f) * (1.0f / FP8MAX));

    const int g = lane >> 2, t = lane & 3;
    #pragma unroll
    for (int mf = 0; mf < 2; mf++) {
        const int r0 = m0 + wm + mf * 16 + g;
        float* row0 = out + (size_t)r0 * N_DIM + n0 + wn;
        float* row1 = row0 + (size_t)8 * N_DIM;
        #pragma unroll
        for (int nf = 0; nf < 8; nf++) {
            const int c = nf * 8 + 2 * t;
            float2 v0 = {acc[mf][nf][0] * inv, acc[mf][nf][1] * inv};
            float2 v1 = {acc[mf][nf][2] * inv, acc[mf][nf][3] * inv};
            *reinterpret_cast<float2*>(row0 + c) = v0;
            *reinterpret_cast<float2*>(row1 + c) = v1;
        }
    }
}

// ---------------- launcher ----------------
extern "C" void kernel_launch(void* const* d_in, const int* in_sizes, int n_in,
                              void* d_out, int out_size) {
    const float* x = (const float*)d_in[0];
    const float* w = (const float*)d_in[1];
    float* out = (float*)d_out;

    int M = in_sizes[0] / K_DIM;  // 16384
    int n4x = in_sizes[0] / 4;
    int n4w = in_sizes[1] / 4;

    cudaFuncSetAttribute(gemm_kernel, cudaFuncAttributeMaxDynamicSharedMemorySize, SMEM_DYN);

    void* amax_ptr = nullptr;
    cudaGetSymbolAddress(&amax_ptr, g_amax_bits);
    cudaMemsetAsync(amax_ptr, 0, 2 * sizeof(unsigned));

    // R12-measured best amax config: 2560 blocks, split 2048:512
    amax2_kernel<<<2560, 256>>>((const float4*)x, n4x, (const float4*)w, n4w, 2048);
    // x-partition widened to 4096 blocks (finer interleave with w tiles)
    quant_both_kernel<<<4096 + 4096, 256>>>((const float4*)x, n4x, w, 4096);
    gemm_kernel<<<dim3(M / BM, N_DIM / BN), 256, SMEM_DYN>>>(out);
}